// round 12
// baseline (speedup 1.0000x reference)
#include <cuda_runtime.h>
#include <cuda_fp16.h>
#include <cstdint>

// ---------------------------------------------------------------------------
// VQ-VAE EMA quantizer: fp16 mma.sync (m16n8k16) + certified interval argmin.
//   vq_main: GEMM + top-2 packed-key argmin -> g_keys
//   vq_out : gather z_embed, exact dist^2, flags, loss partials
//   vq_fix : BATCHED exact fp32 re-argmin (16 rows/block share codebook reads)
// ---------------------------------------------------------------------------

#define BB 131072
#define DD 128
#define KK 1024
#define BM 128
#define BN 64
#define NITER (KK/BN)   // 16
#define FCAP 32768
#define CBOUND 1.05e-3f
#define BIAS 2.0f
#define ARES 6          // kc-steps with A register-resident
#define FB 16           // rows per fix batch

// smem byte offsets (vq_main; 2 CTAs/SM)
#define SM_A    0         // 32KB x fp16, A-frag permuted (+kc XOR swizzle)
#define SM_B    32768     // 2 stages x 16KB e fp16 B-frag permuted
#define SM_P    65536     // 4KB p''_k = p_k - c_k*G + BIAS
#define SM_Q    69632     // 4KB q_k
#define SM_XX   73728     // 512B h_r
#define SM_M1   74240     // 512B packed int
#define SM_M2   74752     // 512B packed int
#define SM_RED  75264     // 64B
#define SMEM_BYTES 75328

__device__ float g_loss;
__device__ int   g_nflag;
__device__ int   g_done;
__device__ int   g_flags[FCAP];
__device__ float g_fest[FCAP];
__device__ float g_p[KK];
__device__ float g_q[KK];
__device__ float g_c[KK];
__device__ float g_Gv[BB / BM];
__device__ uint2 g_keys[BB];
__device__ uint32_t g_eb[KK * DD / 2];   // B-frag permuted fp16 codebook

__device__ __forceinline__ void mma_h(float c[4], const uint4& a, uint32_t b0, uint32_t b1) {
    asm volatile(
        "mma.sync.aligned.m16n8k16.row.col.f32.f16.f16.f32 "
        "{%0,%1,%2,%3},{%4,%5,%6,%7},{%8,%9},{%0,%1,%2,%3};"
        : "+f"(c[0]), "+f"(c[1]), "+f"(c[2]), "+f"(c[3])
        : "r"(a.x), "r"(a.y), "r"(a.z), "r"(a.w), "r"(b0), "r"(b1));
}
__device__ __forceinline__ void cp16(uint32_t dst_smem, const void* src) {
    asm volatile("cp.async.cg.shared.global [%0], [%1], 16;"
                 :: "r"(dst_smem), "l"(src) : "memory");
}
__device__ __forceinline__ uint32_t smem_u32(const void* p) {
    uint32_t a;
    asm("{ .reg .u64 t; cvta.to.shared.u64 t, %1; cvt.u32.u64 %0, t; }"
        : "=r"(a) : "l"(p));
    return a;
}
__device__ __forceinline__ uint32_t h2pack(float lo, float hi) {
    __half2 h = __halves2half2(__float2half_rn(lo), __float2half_rn(hi));
    return *(uint32_t*)&h;
}
// key = (bits(lo) & ~0x3FF) | k  ; lo > 0 guaranteed -> int order == float order
__device__ __forceinline__ int mkkey(float lo, int k) {
    return (__float_as_int(lo) & 0xFFFFFC00) | k;
}

// ---------------------------------------------------------------------------
// prep: fp16 codebook in B-frag layout (64-codeword tiles), p/q/c, resets.
// ---------------------------------------------------------------------------
__global__ void vq_prep(const float* __restrict__ E, const float* __restrict__ S) {
    int wid = threadIdx.x >> 5, lane = threadIdx.x & 31;
    int k = blockIdx.x * 8 + wid;
    float4 v = ((const float4*)(E + (size_t)k * DD))[lane];
    float s2 = v.x * v.x + v.y * v.y + v.z * v.z + v.w * v.w;
    #pragma unroll
    for (int o = 16; o > 0; o >>= 1) s2 += __shfl_xor_sync(0xffffffffu, s2, o);

    int t = k >> 6, n = k & 63;
    int ng = n >> 4, blocksel = (n >> 3) & 1, g = n & 7;
    float e[4] = {v.x, v.y, v.z, v.w};
    #pragma unroll
    for (int j2 = 0; j2 < 2; ++j2) {
        int d0 = 4 * lane + 2 * j2;
        int kc = d0 >> 4;
        int tl = (d0 & 7) >> 1;
        int khi = (d0 >> 3) & 1;
        uint32_t h = h2pack(e[2 * j2], e[2 * j2 + 1]);
        g_eb[(size_t)t * 4096 +
             (size_t)((kc * 4 + ng) * 32 + g * 4 + tl) * 4 + blocksel * 2 + khi] = h;
    }
    if (lane == 0) {
        float s = S[k];
        g_p[k] = s * s2;
        g_q[k] = -2.0f * s;
        g_c[k] = CBOUND * s * sqrtf(s2);
    }
    if (blockIdx.x == 0 && threadIdx.x == 0) { g_loss = 0.0f; g_nflag = 0; g_done = 0; }
}

// ---------------------------------------------------------------------------
// main: 128 rows/CTA vs full codebook; BN=64/iter; warps 4M x 2N.
// GEMM + top-2 keys only; per-row keys -> g_keys, per-CTA G -> g_Gv.
// ---------------------------------------------------------------------------
__global__ __launch_bounds__(256, 2) void vq_main(const float* __restrict__ X)
{
    extern __shared__ char smem[];
    const uint32_t sb = smem_u32(smem);
    const int tid    = threadIdx.x;
    const int lane   = tid & 31;
    const int wid    = tid >> 5;
    const int warp_m = wid >> 1;
    const int warp_n = wid & 1;
    const int b0     = blockIdx.x * BM;

    float* ps  = (float*)(smem + SM_P);
    float* qs  = (float*)(smem + SM_Q);
    float* xx  = (float*)(smem + SM_XX);
    float* red = (float*)(smem + SM_RED);

    // B tile 0 fetch starts immediately
    {
        uint32_t dh = sb + SM_B + tid * 16;
        const char* src = (const char*)g_eb + tid * 16;
        #pragma unroll
        for (int r = 0; r < 4; ++r) cp16(dh + r * 4096, src + r * 4096);
        asm volatile("cp.async.commit_group;" ::: "memory");
    }

    // ---- X tile: load, fp16-round into A-frag layout (kc-XOR swizzle), norms, G ----
    float gmax = 0.0f;
    {
        const float4* Xg = (const float4*)(X + (size_t)b0 * DD);
        uint32_t* A32 = (uint32_t*)(smem + SM_A);
        #pragma unroll
        for (int it = 0; it < 16; ++it) {
            int idx = tid + it * 256;
            int r = idx >> 5;          // uniform per warp
            float4 v = Xg[r * 32 + lane];
            float n = v.x * v.x + v.y * v.y + v.z * v.z + v.w * v.w;
            #pragma unroll
            for (int o = 16; o > 0; o >>= 1) n += __shfl_xor_sync(0xffffffffu, n, o);
            if (lane == 0) xx[r] = -0.5f * n;
            gmax = fmaxf(gmax, n);
            int mtb = r >> 4, g = r & 7, rhigh = (r >> 3) & 1;
            int kc  = lane >> 2;
            int tl  = 2 * (lane & 1);
            int khi = (lane >> 1) & 1;
            int reg = rhigh + 2 * khi;
            int base = (kc * 8 + mtb) * 32;
            A32[(base + ((g * 4 + tl) ^ kc)) * 4 + reg]     = h2pack(v.x, v.y);
            A32[(base + ((g * 4 + tl + 1) ^ kc)) * 4 + reg] = h2pack(v.z, v.w);
        }
    }
    if (lane == 0) red[wid] = gmax;
    __syncthreads();
    float G;
    {
        float g = red[0];
        #pragma unroll
        for (int w = 1; w < 8; ++w) g = fmaxf(g, red[w]);
        G = sqrtf(g) * 1.0001f;
    }
    if (tid == 0) g_Gv[blockIdx.x] = G;
    #pragma unroll
    for (int j = 0; j < 4; ++j) {
        int k = tid + 256 * j;
        ps[k] = g_p[k] - g_c[k] * G + BIAS;
        qs[k] = g_q[k];
    }
    asm volatile("cp.async.wait_group 0;" ::: "memory");
    __syncthreads();

    float hrow[4];
    #pragma unroll
    for (int mt = 0; mt < 2; ++mt)
        #pragma unroll
        for (int pr = 0; pr < 2; ++pr)
            hrow[mt * 2 + pr] = xx[warp_m * 32 + mt * 16 + (lane >> 2) + 8 * pr];

    int m1v[4] = {0x7FFFFFFF, 0x7FFFFFFF, 0x7FFFFFFF, 0x7FFFFFFF};
    int m2v[4] = {0x7FFFFFFF, 0x7FFFFFFF, 0x7FFFFFFF, 0x7FFFFFFF};

    const uint4* A4 = (const uint4*)(smem + SM_A);

    uint4 areg[ARES][2];
    #pragma unroll
    for (int kc = 0; kc < ARES; ++kc) {
        int ls = lane ^ kc;
        areg[kc][0] = A4[(kc * 8 + warp_m * 2) * 32 + ls];
        areg[kc][1] = A4[(kc * 8 + warp_m * 2 + 1) * 32 + ls];
    }

    const int klane = (lane & 3) << 1;

    for (int t = 0; t < NITER; ++t) {
        const int stage = t & 1;
        if (t + 1 < NITER) {
            uint32_t dh = sb + SM_B + (stage ^ 1) * 16384 + tid * 16;
            const char* src = (const char*)g_eb + (size_t)(t + 1) * 16384 + tid * 16;
            #pragma unroll
            for (int r = 0; r < 4; ++r) cp16(dh + r * 4096, src + r * 4096);
            asm volatile("cp.async.commit_group;" ::: "memory");
        }

        const uint4* B4 = (const uint4*)(smem + SM_B + stage * 16384);

        float acc[2][4][4];
        #pragma unroll
        for (int mt = 0; mt < 2; ++mt)
            #pragma unroll
            for (int nb = 0; nb < 4; ++nb) {
                acc[mt][nb][0] = hrow[mt * 2];
                acc[mt][nb][1] = hrow[mt * 2];
                acc[mt][nb][2] = hrow[mt * 2 + 1];
                acc[mt][nb][3] = hrow[mt * 2 + 1];
            }

        uint4 a0 = areg[0][0], a1 = areg[0][1];
        uint4 bb0 = B4[(warp_n * 2) * 32 + lane];
        uint4 bb1 = B4[(warp_n * 2 + 1) * 32 + lane];
        #pragma unroll
        for (int kc = 0; kc < 8; ++kc) {
            uint4 a0n, a1n, b0n, b1n;
            if (kc < 7) {
                int kn = kc + 1;
                b0n = B4[(kn * 4 + warp_n * 2) * 32 + lane];
                b1n = B4[(kn * 4 + warp_n * 2 + 1) * 32 + lane];
                if (kn < ARES) {
                    a0n = areg[kn][0]; a1n = areg[kn][1];
                } else {
                    int ls = lane ^ kn;
                    a0n = A4[(kn * 8 + warp_m * 2) * 32 + ls];
                    a1n = A4[(kn * 8 + warp_m * 2 + 1) * 32 + ls];
                }
            }
            mma_h(acc[0][0], a0, bb0.x, bb0.y);
            mma_h(acc[0][1], a0, bb0.z, bb0.w);
            mma_h(acc[0][2], a0, bb1.x, bb1.y);
            mma_h(acc[0][3], a0, bb1.z, bb1.w);
            mma_h(acc[1][0], a1, bb0.x, bb0.y);
            mma_h(acc[1][1], a1, bb0.z, bb0.w);
            mma_h(acc[1][2], a1, bb1.x, bb1.y);
            mma_h(acc[1][3], a1, bb1.z, bb1.w);
            if (kc < 7) { a0 = a0n; a1 = a1n; bb0 = b0n; bb1 = b1n; }
        }

        #pragma unroll
        for (int ntg = 0; ntg < 2; ++ntg) {
            #pragma unroll
            for (int blk = 0; blk < 2; ++blk) {
                int nb = ntg * 2 + blk;
                int k0 = t * 64 + (warp_n * 2 + ntg) * 16 + blk * 8 + klane;
                float2 pp = *(const float2*)(ps + k0);
                float2 qq = *(const float2*)(qs + k0);
                #pragma unroll
                for (int mt = 0; mt < 2; ++mt) {
                    #pragma unroll
                    for (int pr = 0; pr < 2; ++pr) {
                        int rs = mt * 2 + pr;
                        int key0 = mkkey(fmaf(qq.x, acc[mt][nb][pr * 2 + 0], pp.x), k0);
                        int key1 = mkkey(fmaf(qq.y, acc[mt][nb][pr * 2 + 1], pp.y), k0 + 1);
                        m2v[rs] = min(m2v[rs], max(m1v[rs], key0));
                        m1v[rs] = min(m1v[rs], key0);
                        m2v[rs] = min(m2v[rs], max(m1v[rs], key1));
                        m1v[rs] = min(m1v[rs], key1);
                    }
                }
            }
        }

        asm volatile("cp.async.wait_group 0;" ::: "memory");
        __syncthreads();
    }

    #pragma unroll
    for (int o = 1; o <= 2; o <<= 1) {
        #pragma unroll
        for (int rs = 0; rs < 4; ++rs) {
            int om1 = __shfl_xor_sync(0xffffffffu, m1v[rs], o);
            int om2 = __shfl_xor_sync(0xffffffffu, m2v[rs], o);
            m2v[rs] = min(min(m2v[rs], om2), max(m1v[rs], om1));
            m1v[rs] = min(m1v[rs], om1);
        }
    }
    int* sm1 = (int*)(smem + SM_M1);
    int* sm2 = (int*)(smem + SM_M2);
    if (warp_n == 0 && (lane & 3) == 0) {
        #pragma unroll
        for (int rs = 0; rs < 4; ++rs) {
            int row = warp_m * 32 + (rs >> 1) * 16 + (lane >> 2) + (rs & 1) * 8;
            sm1[row] = m1v[rs]; sm2[row] = m2v[rs];
        }
    }
    __syncthreads();
    if (warp_n == 1 && (lane & 3) == 0) {
        #pragma unroll
        for (int rs = 0; rs < 4; ++rs) {
            int row = warp_m * 32 + (rs >> 1) * 16 + (lane >> 2) + (rs & 1) * 8;
            int a1 = sm1[row], a2 = sm2[row];
            sm2[row] = min(min(a2, m2v[rs]), max(a1, m1v[rs]));
            sm1[row] = min(a1, m1v[rs]);
        }
    }
    __syncthreads();

    if (tid < BM) g_keys[b0 + tid] = make_uint2((uint32_t)sm1[tid], (uint32_t)sm2[tid]);
}

// ---------------------------------------------------------------------------
// out: gather z_embed, exact per-row dist^2, indices, flags, loss partials.
// ---------------------------------------------------------------------------
__global__ __launch_bounds__(256) void vq_out(
    const float* __restrict__ X, const float* __restrict__ E,
    float* __restrict__ out, int out_size)
{
    __shared__ float dd[BM];
    __shared__ float red[8];
    const int tid = threadIdx.x;
    const int b0  = blockIdx.x * BM;

    {
        int r = tid >> 1, hf = tid & 1;
        uint32_t key = g_keys[b0 + r].x;
        int idx = key & 1023;
        const float4* Eq = (const float4*)(E + (size_t)idx * DD) + hf * 16;
        const float4* Xq = (const float4*)(X + (size_t)(b0 + r) * DD) + hf * 16;
        float4* Oq = (float4*)(out + (size_t)(b0 + r) * DD) + hf * 16;
        float dsum = 0.0f;
        #pragma unroll
        for (int j = 0; j < 16; ++j) {
            float4 q = Eq[j];
            float4 x = Xq[j];
            float d0 = q.x - x.x, d1 = q.y - x.y, d2 = q.z - x.z, d3 = q.w - x.w;
            dsum += d0 * d0 + d1 * d1 + d2 * d2 + d3 * d3;
            Oq[j] = q;
        }
        dsum += __shfl_xor_sync(0xffffffffu, dsum, 1);
        if (hf == 0) dd[r] = dsum;
    }
    __syncthreads();

    const bool full = (out_size >= BB * DD + 1 + BB);
    float lsum = 0.0f;
    if (tid < BM) {
        uint2 pk = g_keys[b0 + tid];
        int pm1 = (int)pk.x, pm2 = (int)pk.y;
        int kk = pm1 & 1023;
        float v1 = __int_as_float(pm1 & 0xFFFFFC00) - BIAS;
        float v2 = __int_as_float(pm2 & 0xFFFFFC00) - BIAS;
        float b1 = g_c[kk] * g_Gv[blockIdx.x];
        if (full) out[(size_t)BB * DD + 1 + b0 + tid] = (float)kk;
        float dex = dd[tid];
        float slack = 2.05f * b1 + 3e-4f * (v1 + BIAS) + 1e-4f;
        if (v2 <= v1 + slack && full) {
            int pos = atomicAdd(&g_nflag, 1);
            if (pos < FCAP) { g_flags[pos] = b0 + tid; g_fest[pos] = dex; }
        }
        lsum = dex;
    }
    #pragma unroll
    for (int o = 16; o > 0; o >>= 1) lsum += __shfl_xor_sync(0xffffffffu, lsum, o);
    if ((tid & 31) == 0) red[tid >> 5] = lsum;
    __syncthreads();
    if (tid == 0) atomicAdd(&g_loss, red[0] + red[1] + red[2] + red[3]);
}

// ---------------------------------------------------------------------------
// fix: BATCHED exact fp32 argmin for flagged rows. 16 rows/block share the
// codebook pass: thread (r = tid&15, c = tid>>4) scans codewords c+16*kk.
// e-row loads broadcast across the 16 lanes sharing a codeword.
// ---------------------------------------------------------------------------
__global__ __launch_bounds__(256) void vq_fix(
    const float* __restrict__ X, const float* __restrict__ E,
    float* __restrict__ out, int out_size)
{
    __shared__ float xs[FB][132];
    __shared__ float hh[FB];
    __shared__ float rv[FB][17];
    __shared__ int   rk[FB][17];
    __shared__ int   rowid[FB];
    __shared__ int   newk[FB];

    const int tid = threadIdx.x;
    int n = 0;
    if (out_size >= BB * DD + 1 + BB) {
        n = g_nflag;
        if (n > FCAP) n = FCAP;
    }

    for (int base = blockIdx.x * FB; base < n; base += gridDim.x * FB) {
        const int cnt = min(FB, n - base);

        // stage x rows (32 float4 per row)
        for (int i = tid; i < cnt * 32; i += 256) {
            int r = i >> 5, j = i & 31;
            int row = g_flags[base + r];
            if (j == 0) rowid[r] = row;
            *(float4*)&xs[r][j * 4] = ((const float4*)(X + (size_t)row * DD))[j];
        }
        __syncthreads();
        if (tid < cnt) {
            float s = 0.0f;
            #pragma unroll 8
            for (int d = 0; d < DD; ++d) s = fmaf(xs[tid][d], xs[tid][d], s);
            hh[tid] = -0.5f * s;
        }
        __syncthreads();

        // scan codebook: each thread 64 codewords for its row
        const int r = tid & 15, c = tid >> 4;
        float best = 3.4e38f; int bk = 0;
        if (r < cnt) {
            float h = hh[r];
            for (int kk = 0; kk < 64; ++kk) {
                int k = c + (kk << 4);
                const float4* e4 = (const float4*)(E + (size_t)k * DD);
                float dot = 0.0f;
                #pragma unroll 8
                for (int j = 0; j < 32; ++j) {
                    float4 e = e4[j];
                    const float* xp = &xs[r][j * 4];
                    dot = fmaf(e.x, xp[0], dot);
                    dot = fmaf(e.y, xp[1], dot);
                    dot = fmaf(e.z, xp[2], dot);
                    dot = fmaf(e.w, xp[3], dot);
                }
                float v = g_p[k] + g_q[k] * (dot + h);
                if (v < best) { best = v; bk = k; }
            }
        }
        rv[r][c] = best; rk[r][c] = bk;
        __syncthreads();

        // per-row reduce + apply correction
        if (tid < cnt) {
            float bv = rv[tid][0]; int bkr = rk[tid][0];
            #pragma unroll
            for (int cc = 1; cc < 16; ++cc) {
                float ov = rv[tid][cc]; int ok = rk[tid][cc];
                if (ov < bv || (ov == bv && ok < bkr)) { bv = ov; bkr = ok; }
            }
            int row = rowid[tid];
            int kold = (int)out[(size_t)BB * DD + 1 + row];
            if (bkr != kold) {
                out[(size_t)BB * DD + 1 + row] = (float)bkr;
                float dnew = -2.0f * bv / g_q[bkr];
                atomicAdd(&g_loss, dnew - g_fest[base + tid]);
                newk[tid] = bkr;
            } else {
                newk[tid] = -1;
            }
        }
        __syncthreads();

        // rewrite z rows that changed (16 threads per row, 2 float4 each)
        {
            int kb = (r < cnt) ? newk[r] : -1;
            if (kb >= 0) {
                int row = rowid[r];
                const float4* Eq = (const float4*)(E + (size_t)kb * DD);
                float4* Oq = (float4*)(out + (size_t)row * DD);
                Oq[c * 2]     = Eq[c * 2];
                Oq[c * 2 + 1] = Eq[c * 2 + 1];
            }
        }
        __syncthreads();
    }

    // last block to finish writes the final loss scalar
    if (tid == 0) {
        __threadfence();
        int d = atomicAdd(&g_done, 1);
        if (d == (int)gridDim.x - 1 && out_size >= BB * DD + 1) {
            out[(size_t)BB * DD] = 0.25f * g_loss / (float)((size_t)BB * DD);
        }
    }
}

extern "C" void kernel_launch(void* const* d_in, const int* in_sizes, int n_in,
                              void* d_out, int out_size) {
    const float* X = (const float*)d_in[0];
    const float* E = (const float*)d_in[1];
    const float* S = (const float*)d_in[2];
    float* out = (float*)d_out;

    cudaFuncSetAttribute(vq_main, cudaFuncAttributeMaxDynamicSharedMemorySize, SMEM_BYTES);

    vq_prep<<<KK / 8, 256>>>(E, S);
    vq_main<<<BB / BM, 256, SMEM_BYTES>>>(X);
    vq_out<<<BB / BM, 256>>>(X, E, out, out_size);
    vq_fix<<<512, 256>>>(X, E, out, out_size);
}

// round 13
// speedup vs baseline: 2.4734x; 2.4734x over previous
#include <cuda_runtime.h>
#include <cuda_fp16.h>
#include <cstdint>

// ---------------------------------------------------------------------------
// VQ-VAE EMA quantizer: fp16 mma.sync (m16n8k16) + certified interval argmin.
//   vq_main: GEMM + top-2 packed-key argmin -> g_keys
//   vq_out : gather z_embed, exact dist^2, flags (+h, fixkey init), loss
//   vq_fix1: codebook-stationary exact fp32 rescan of flagged rows,
//            64-bit packed-key atomicMin (full fp32 precision)
//   vq_fix2: apply corrections + final loss scalar
// ---------------------------------------------------------------------------

#define BB 131072
#define DD 128
#define KK 1024
#define BM 128
#define BN 64
#define NITER (KK/BN)   // 16
#define FCAP 32768
#define CBOUND 1.05e-3f
#define BIAS 2.0f
#define ARES 6          // kc-steps with A register-resident

// fix1 geometry: 32 slices x 32 codewords; 8 rows per pass; 16 row groups
#define SLICEK 32
#define NSLICE (KK/SLICEK)   // 32
#define RPP 8
#define NRG 16
#define FIX1_GRID (NSLICE*NRG)   // 512

// smem byte offsets (vq_main; 2 CTAs/SM)
#define SM_A    0         // 32KB x fp16, A-frag permuted (+kc XOR swizzle)
#define SM_B    32768     // 2 stages x 16KB e fp16 B-frag permuted
#define SM_P    65536     // 4KB p''_k
#define SM_Q    69632     // 4KB q_k
#define SM_XX   73728     // 512B h_r
#define SM_M1   74240     // 512B packed int
#define SM_M2   74752     // 512B packed int
#define SM_RED  75264     // 64B
#define SMEM_BYTES 75328

__device__ float g_loss;
__device__ int   g_nflag;
__device__ int   g_done;
__device__ int   g_flags[FCAP];
__device__ float g_fest[FCAP];
__device__ float g_fh[FCAP];
__device__ unsigned long long g_fixkey[FCAP];
__device__ float g_p[KK];
__device__ float g_q[KK];
__device__ float g_c[KK];
__device__ float g_Gv[BB / BM];
__device__ uint2 g_keys[BB];
__device__ uint32_t g_eb[KK * DD / 2];   // B-frag permuted fp16 codebook

__device__ __forceinline__ void mma_h(float c[4], const uint4& a, uint32_t b0, uint32_t b1) {
    asm volatile(
        "mma.sync.aligned.m16n8k16.row.col.f32.f16.f16.f32 "
        "{%0,%1,%2,%3},{%4,%5,%6,%7},{%8,%9},{%0,%1,%2,%3};"
        : "+f"(c[0]), "+f"(c[1]), "+f"(c[2]), "+f"(c[3])
        : "r"(a.x), "r"(a.y), "r"(a.z), "r"(a.w), "r"(b0), "r"(b1));
}
__device__ __forceinline__ void cp16(uint32_t dst_smem, const void* src) {
    asm volatile("cp.async.cg.shared.global [%0], [%1], 16;"
                 :: "r"(dst_smem), "l"(src) : "memory");
}
__device__ __forceinline__ uint32_t smem_u32(const void* p) {
    uint32_t a;
    asm("{ .reg .u64 t; cvta.to.shared.u64 t, %1; cvt.u32.u64 %0, t; }"
        : "=r"(a) : "l"(p));
    return a;
}
__device__ __forceinline__ uint32_t h2pack(float lo, float hi) {
    __half2 h = __halves2half2(__float2half_rn(lo), __float2half_rn(hi));
    return *(uint32_t*)&h;
}
__device__ __forceinline__ int mkkey(float lo, int k) {
    return (__float_as_int(lo) & 0xFFFFFC00) | k;
}

// ---------------------------------------------------------------------------
// prep
// ---------------------------------------------------------------------------
__global__ void vq_prep(const float* __restrict__ E, const float* __restrict__ S) {
    int wid = threadIdx.x >> 5, lane = threadIdx.x & 31;
    int k = blockIdx.x * 8 + wid;
    float4 v = ((const float4*)(E + (size_t)k * DD))[lane];
    float s2 = v.x * v.x + v.y * v.y + v.z * v.z + v.w * v.w;
    #pragma unroll
    for (int o = 16; o > 0; o >>= 1) s2 += __shfl_xor_sync(0xffffffffu, s2, o);

    int t = k >> 6, n = k & 63;
    int ng = n >> 4, blocksel = (n >> 3) & 1, g = n & 7;
    float e[4] = {v.x, v.y, v.z, v.w};
    #pragma unroll
    for (int j2 = 0; j2 < 2; ++j2) {
        int d0 = 4 * lane + 2 * j2;
        int kc = d0 >> 4;
        int tl = (d0 & 7) >> 1;
        int khi = (d0 >> 3) & 1;
        uint32_t h = h2pack(e[2 * j2], e[2 * j2 + 1]);
        g_eb[(size_t)t * 4096 +
             (size_t)((kc * 4 + ng) * 32 + g * 4 + tl) * 4 + blocksel * 2 + khi] = h;
    }
    if (lane == 0) {
        float s = S[k];
        g_p[k] = s * s2;
        g_q[k] = -2.0f * s;
        g_c[k] = CBOUND * s * sqrtf(s2);
    }
    if (blockIdx.x == 0 && threadIdx.x == 0) { g_loss = 0.0f; g_nflag = 0; g_done = 0; }
}

// ---------------------------------------------------------------------------
// main: identical to R11 (proven): GEMM + top-2 keys -> g_keys
// ---------------------------------------------------------------------------
__global__ __launch_bounds__(256, 2) void vq_main(const float* __restrict__ X)
{
    extern __shared__ char smem[];
    const uint32_t sb = smem_u32(smem);
    const int tid    = threadIdx.x;
    const int lane   = tid & 31;
    const int wid    = tid >> 5;
    const int warp_m = wid >> 1;
    const int warp_n = wid & 1;
    const int b0     = blockIdx.x * BM;

    float* ps  = (float*)(smem + SM_P);
    float* qs  = (float*)(smem + SM_Q);
    float* xx  = (float*)(smem + SM_XX);
    float* red = (float*)(smem + SM_RED);

    {
        uint32_t dh = sb + SM_B + tid * 16;
        const char* src = (const char*)g_eb + tid * 16;
        #pragma unroll
        for (int r = 0; r < 4; ++r) cp16(dh + r * 4096, src + r * 4096);
        asm volatile("cp.async.commit_group;" ::: "memory");
    }

    float gmax = 0.0f;
    {
        const float4* Xg = (const float4*)(X + (size_t)b0 * DD);
        uint32_t* A32 = (uint32_t*)(smem + SM_A);
        #pragma unroll
        for (int it = 0; it < 16; ++it) {
            int idx = tid + it * 256;
            int r = idx >> 5;
            float4 v = Xg[r * 32 + lane];
            float n = v.x * v.x + v.y * v.y + v.z * v.z + v.w * v.w;
            #pragma unroll
            for (int o = 16; o > 0; o >>= 1) n += __shfl_xor_sync(0xffffffffu, n, o);
            if (lane == 0) xx[r] = -0.5f * n;
            gmax = fmaxf(gmax, n);
            int mtb = r >> 4, g = r & 7, rhigh = (r >> 3) & 1;
            int kc  = lane >> 2;
            int tl  = 2 * (lane & 1);
            int khi = (lane >> 1) & 1;
            int reg = rhigh + 2 * khi;
            int base = (kc * 8 + mtb) * 32;
            A32[(base + ((g * 4 + tl) ^ kc)) * 4 + reg]     = h2pack(v.x, v.y);
            A32[(base + ((g * 4 + tl + 1) ^ kc)) * 4 + reg] = h2pack(v.z, v.w);
        }
    }
    if (lane == 0) red[wid] = gmax;
    __syncthreads();
    float G;
    {
        float g = red[0];
        #pragma unroll
        for (int w = 1; w < 8; ++w) g = fmaxf(g, red[w]);
        G = sqrtf(g) * 1.0001f;
    }
    if (tid == 0) g_Gv[blockIdx.x] = G;
    #pragma unroll
    for (int j = 0; j < 4; ++j) {
        int k = tid + 256 * j;
        ps[k] = g_p[k] - g_c[k] * G + BIAS;
        qs[k] = g_q[k];
    }
    asm volatile("cp.async.wait_group 0;" ::: "memory");
    __syncthreads();

    float hrow[4];
    #pragma unroll
    for (int mt = 0; mt < 2; ++mt)
        #pragma unroll
        for (int pr = 0; pr < 2; ++pr)
            hrow[mt * 2 + pr] = xx[warp_m * 32 + mt * 16 + (lane >> 2) + 8 * pr];

    int m1v[4] = {0x7FFFFFFF, 0x7FFFFFFF, 0x7FFFFFFF, 0x7FFFFFFF};
    int m2v[4] = {0x7FFFFFFF, 0x7FFFFFFF, 0x7FFFFFFF, 0x7FFFFFFF};

    const uint4* A4 = (const uint4*)(smem + SM_A);
    uint4 areg[ARES][2];
    #pragma unroll
    for (int kc = 0; kc < ARES; ++kc) {
        int ls = lane ^ kc;
        areg[kc][0] = A4[(kc * 8 + warp_m * 2) * 32 + ls];
        areg[kc][1] = A4[(kc * 8 + warp_m * 2 + 1) * 32 + ls];
    }

    const int klane = (lane & 3) << 1;

    for (int t = 0; t < NITER; ++t) {
        const int stage = t & 1;
        if (t + 1 < NITER) {
            uint32_t dh = sb + SM_B + (stage ^ 1) * 16384 + tid * 16;
            const char* src = (const char*)g_eb + (size_t)(t + 1) * 16384 + tid * 16;
            #pragma unroll
            for (int r = 0; r < 4; ++r) cp16(dh + r * 4096, src + r * 4096);
            asm volatile("cp.async.commit_group;" ::: "memory");
        }

        const uint4* B4 = (const uint4*)(smem + SM_B + stage * 16384);

        float acc[2][4][4];
        #pragma unroll
        for (int mt = 0; mt < 2; ++mt)
            #pragma unroll
            for (int nb = 0; nb < 4; ++nb) {
                acc[mt][nb][0] = hrow[mt * 2];
                acc[mt][nb][1] = hrow[mt * 2];
                acc[mt][nb][2] = hrow[mt * 2 + 1];
                acc[mt][nb][3] = hrow[mt * 2 + 1];
            }

        uint4 a0 = areg[0][0], a1 = areg[0][1];
        uint4 bb0 = B4[(warp_n * 2) * 32 + lane];
        uint4 bb1 = B4[(warp_n * 2 + 1) * 32 + lane];
        #pragma unroll
        for (int kc = 0; kc < 8; ++kc) {
            uint4 a0n, a1n, b0n, b1n;
            if (kc < 7) {
                int kn = kc + 1;
                b0n = B4[(kn * 4 + warp_n * 2) * 32 + lane];
                b1n = B4[(kn * 4 + warp_n * 2 + 1) * 32 + lane];
                if (kn < ARES) {
                    a0n = areg[kn][0]; a1n = areg[kn][1];
                } else {
                    int ls = lane ^ kn;
                    a0n = A4[(kn * 8 + warp_m * 2) * 32 + ls];
                    a1n = A4[(kn * 8 + warp_m * 2 + 1) * 32 + ls];
                }
            }
            mma_h(acc[0][0], a0, bb0.x, bb0.y);
            mma_h(acc[0][1], a0, bb0.z, bb0.w);
            mma_h(acc[0][2], a0, bb1.x, bb1.y);
            mma_h(acc[0][3], a0, bb1.z, bb1.w);
            mma_h(acc[1][0], a1, bb0.x, bb0.y);
            mma_h(acc[1][1], a1, bb0.z, bb0.w);
            mma_h(acc[1][2], a1, bb1.x, bb1.y);
            mma_h(acc[1][3], a1, bb1.z, bb1.w);
            if (kc < 7) { a0 = a0n; a1 = a1n; bb0 = b0n; bb1 = b1n; }
        }

        #pragma unroll
        for (int ntg = 0; ntg < 2; ++ntg) {
            #pragma unroll
            for (int blk = 0; blk < 2; ++blk) {
                int nb = ntg * 2 + blk;
                int k0 = t * 64 + (warp_n * 2 + ntg) * 16 + blk * 8 + klane;
                float2 pp = *(const float2*)(ps + k0);
                float2 qq = *(const float2*)(qs + k0);
                #pragma unroll
                for (int mt = 0; mt < 2; ++mt) {
                    #pragma unroll
                    for (int pr = 0; pr < 2; ++pr) {
                        int rs = mt * 2 + pr;
                        int key0 = mkkey(fmaf(qq.x, acc[mt][nb][pr * 2 + 0], pp.x), k0);
                        int key1 = mkkey(fmaf(qq.y, acc[mt][nb][pr * 2 + 1], pp.y), k0 + 1);
                        m2v[rs] = min(m2v[rs], max(m1v[rs], key0));
                        m1v[rs] = min(m1v[rs], key0);
                        m2v[rs] = min(m2v[rs], max(m1v[rs], key1));
                        m1v[rs] = min(m1v[rs], key1);
                    }
                }
            }
        }

        asm volatile("cp.async.wait_group 0;" ::: "memory");
        __syncthreads();
    }

    #pragma unroll
    for (int o = 1; o <= 2; o <<= 1) {
        #pragma unroll
        for (int rs = 0; rs < 4; ++rs) {
            int om1 = __shfl_xor_sync(0xffffffffu, m1v[rs], o);
            int om2 = __shfl_xor_sync(0xffffffffu, m2v[rs], o);
            m2v[rs] = min(min(m2v[rs], om2), max(m1v[rs], om1));
            m1v[rs] = min(m1v[rs], om1);
        }
    }
    int* sm1 = (int*)(smem + SM_M1);
    int* sm2 = (int*)(smem + SM_M2);
    if (warp_n == 0 && (lane & 3) == 0) {
        #pragma unroll
        for (int rs = 0; rs < 4; ++rs) {
            int row = warp_m * 32 + (rs >> 1) * 16 + (lane >> 2) + (rs & 1) * 8;
            sm1[row] = m1v[rs]; sm2[row] = m2v[rs];
        }
    }
    __syncthreads();
    if (warp_n == 1 && (lane & 3) == 0) {
        #pragma unroll
        for (int rs = 0; rs < 4; ++rs) {
            int row = warp_m * 32 + (rs >> 1) * 16 + (lane >> 2) + (rs & 1) * 8;
            int a1 = sm1[row], a2 = sm2[row];
            sm2[row] = min(min(a2, m2v[rs]), max(a1, m1v[rs]));
            sm1[row] = min(a1, m1v[rs]);
        }
    }
    __syncthreads();

    if (tid < BM) g_keys[b0 + tid] = make_uint2((uint32_t)sm1[tid], (uint32_t)sm2[tid]);
}

// ---------------------------------------------------------------------------
// out: gather z_embed, exact dist^2 + ||x||^2, indices, flags, loss partials.
// ---------------------------------------------------------------------------
__global__ __launch_bounds__(256) void vq_out(
    const float* __restrict__ X, const float* __restrict__ E,
    float* __restrict__ out, int out_size)
{
    __shared__ float dd[BM];
    __shared__ float xn[BM];
    __shared__ float red[8];
    const int tid = threadIdx.x;
    const int b0  = blockIdx.x * BM;

    {
        int r = tid >> 1, hf = tid & 1;
        uint32_t key = g_keys[b0 + r].x;
        int idx = key & 1023;
        const float4* Eq = (const float4*)(E + (size_t)idx * DD) + hf * 16;
        const float4* Xq = (const float4*)(X + (size_t)(b0 + r) * DD) + hf * 16;
        float4* Oq = (float4*)(out + (size_t)(b0 + r) * DD) + hf * 16;
        float dsum = 0.0f, xsum = 0.0f;
        #pragma unroll
        for (int j = 0; j < 16; ++j) {
            float4 q = Eq[j];
            float4 x = Xq[j];
            float d0 = q.x - x.x, d1 = q.y - x.y, d2 = q.z - x.z, d3 = q.w - x.w;
            dsum += d0 * d0 + d1 * d1 + d2 * d2 + d3 * d3;
            xsum += x.x * x.x + x.y * x.y + x.z * x.z + x.w * x.w;
            Oq[j] = q;
        }
        dsum += __shfl_xor_sync(0xffffffffu, dsum, 1);
        xsum += __shfl_xor_sync(0xffffffffu, xsum, 1);
        if (hf == 0) { dd[r] = dsum; xn[r] = xsum; }
    }
    __syncthreads();

    const bool full = (out_size >= BB * DD + 1 + BB);
    float lsum = 0.0f;
    if (tid < BM) {
        uint2 pk = g_keys[b0 + tid];
        int pm1 = (int)pk.x, pm2 = (int)pk.y;
        int kk = pm1 & 1023;
        float v1 = __int_as_float(pm1 & 0xFFFFFC00) - BIAS;
        float v2 = __int_as_float(pm2 & 0xFFFFFC00) - BIAS;
        float b1 = g_c[kk] * g_Gv[blockIdx.x];
        if (full) out[(size_t)BB * DD + 1 + b0 + tid] = (float)kk;
        float dex = dd[tid];
        float slack = 2.05f * b1 + 3e-4f * (v1 + BIAS) + 1e-4f;
        if (v2 <= v1 + slack && full) {
            int pos = atomicAdd(&g_nflag, 1);
            if (pos < FCAP) {
                g_flags[pos] = b0 + tid;
                g_fest[pos] = dex;
                g_fh[pos] = -0.5f * xn[tid];
                g_fixkey[pos] = 0xFFFFFFFFFFFFFFFFull;
            }
        }
        lsum = dex;
    }
    #pragma unroll
    for (int o = 16; o > 0; o >>= 1) lsum += __shfl_xor_sync(0xffffffffu, lsum, o);
    if ((tid & 31) == 0) red[tid >> 5] = lsum;
    __syncthreads();
    if (tid == 0) atomicAdd(&g_loss, red[0] + red[1] + red[2] + red[3]);
}

// ---------------------------------------------------------------------------
// fix1: codebook-stationary exact rescan. Block = (slice of 32 codewords) x
// (row group). 256 threads = 8 row-slots x 32 codewords. Full-precision
// packed key (f32_bits<<32 | k) -> atomicMin per flagged row.
// ---------------------------------------------------------------------------
__global__ __launch_bounds__(256) void vq_fix1(
    const float* __restrict__ X, const float* __restrict__ E, int out_size)
{
    __shared__ float es[SLICEK][129];
    __shared__ float xs[2][RPP][DD];

    int n = 0;
    if (out_size >= BB * DD + 1 + BB) {
        n = g_nflag;
        if (n > FCAP) n = FCAP;
    }
    const int tid   = threadIdx.x;
    const int slice = blockIdx.x & (NSLICE - 1);
    const int rg    = blockIdx.x / NSLICE;          // 0..NRG-1
    const int slot  = tid >> 5;                     // 0..7
    const int c     = tid & 31;                     // codeword within slice
    const int k     = slice * SLICEK + c;

    // load codebook slice into smem (stride 129 -> conflict-free)
    {
        const float4* Eb = (const float4*)(E + (size_t)slice * SLICEK * DD);
        for (int i = tid; i < SLICEK * 32; i += 256) {
            int cc = i >> 5, j = i & 31;
            float4 v = Eb[cc * 32 + j];
            es[cc][j * 4 + 0] = v.x;
            es[cc][j * 4 + 1] = v.y;
            es[cc][j * 4 + 2] = v.z;
            es[cc][j * 4 + 3] = v.w;
        }
    }
    const float pk = g_p[k];
    const float qk = g_q[k];

    const int i0 = rg * RPP;
    const int stride = NRG * RPP;   // 128 rows per wave

    // prologue: load rows i0..i0+7 into xs[0]
    if (i0 < n) {
        int i = i0 + slot;
        if (i < n) {
            int row = g_flags[i];
            uint32_t dst = smem_u32(&xs[0][slot][(c) * 4]);
            cp16(dst, X + (size_t)row * DD + c * 4);
        }
        asm volatile("cp.async.commit_group;" ::: "memory");
    }

    int buf = 0;
    for (int base = i0; base < n; base += stride, buf ^= 1) {
        asm volatile("cp.async.wait_group 0;" ::: "memory");
        __syncthreads();
        // prefetch next wave
        if (base + stride < n) {
            int i = base + stride + slot;
            if (i < n) {
                int row = g_flags[i];
                uint32_t dst = smem_u32(&xs[buf ^ 1][slot][c * 4]);
                cp16(dst, X + (size_t)row * DD + c * 4);
            }
            asm volatile("cp.async.commit_group;" ::: "memory");
        }

        int i = base + slot;
        unsigned long long key = 0xFFFFFFFFFFFFFFFFull;
        if (i < n) {
            float h = g_fh[i];
            float dot = 0.0f;
            const float* xr = xs[buf][slot];
            #pragma unroll 16
            for (int d = 0; d < DD; ++d) dot = fmaf(es[c][d], xr[d], dot);
            float v = fmaf(qk, dot + h, pk);
            key = ((unsigned long long)__float_as_uint(v) << 32) | (unsigned)k;
        }
        // warp min (warp == one slot, 32 codewords)
        #pragma unroll
        for (int o = 16; o > 0; o >>= 1) {
            unsigned long long ok = __shfl_xor_sync(0xffffffffu, key, o);
            if (ok < key) key = ok;
        }
        if (c == 0 && i < n) atomicMin(&g_fixkey[i], key);
        __syncthreads();
    }
}

// ---------------------------------------------------------------------------
// fix2: apply corrections for flagged rows; final loss scalar.
// ---------------------------------------------------------------------------
__global__ __launch_bounds__(256) void vq_fix2(
    const float* __restrict__ E, float* __restrict__ out, int out_size)
{
    int n = 0;
    if (out_size >= BB * DD + 1 + BB) {
        n = g_nflag;
        if (n > FCAP) n = FCAP;
    }
    for (int i = blockIdx.x * 256 + threadIdx.x; i < n; i += gridDim.x * 256) {
        int row = g_flags[i];
        unsigned long long key = g_fixkey[i];
        int bk = (int)(key & 1023u);
        float v = __uint_as_float((uint32_t)(key >> 32));
        int kold = (int)out[(size_t)BB * DD + 1 + row];
        if (bk != kold) {
            out[(size_t)BB * DD + 1 + row] = (float)bk;
            float dnew = -2.0f * v / g_q[bk];
            atomicAdd(&g_loss, dnew - g_fest[i]);
            const float4* Eq = (const float4*)(E + (size_t)bk * DD);
            float4* Oq = (float4*)(out + (size_t)row * DD);
            #pragma unroll 8
            for (int j = 0; j < 32; ++j) Oq[j] = Eq[j];
        }
    }
    __syncthreads();
    if (threadIdx.x == 0) {
        __threadfence();
        int d = atomicAdd(&g_done, 1);
        if (d == (int)gridDim.x - 1 && out_size >= BB * DD + 1) {
            out[(size_t)BB * DD] = 0.25f * g_loss / (float)((size_t)BB * DD);
        }
    }
}

extern "C" void kernel_launch(void* const* d_in, const int* in_sizes, int n_in,
                              void* d_out, int out_size) {
    const float* X = (const float*)d_in[0];
    const float* E = (const float*)d_in[1];
    const float* S = (const float*)d_in[2];
    float* out = (float*)d_out;

    cudaFuncSetAttribute(vq_main, cudaFuncAttributeMaxDynamicSharedMemorySize, SMEM_BYTES);

    vq_prep<<<KK / 8, 256>>>(E, S);
    vq_main<<<BB / BM, 256, SMEM_BYTES>>>(X);
    vq_out<<<BB / BM, 256>>>(X, E, out, out_size);
    vq_fix1<<<FIX1_GRID, 256>>>(X, E, out_size);
    vq_fix2<<<128, 256>>>(E, out, out_size);
}